// round 3
// baseline (speedup 1.0000x reference)
#include <cuda_runtime.h>
#include <math.h>
#include <stdint.h>

// ---------------------------------------------------------------------------
// Problem constants
// ---------------------------------------------------------------------------
constexpr int cB  = 32;
constexpr int cH  = 56;
constexpr int cW  = 56;
constexpr int cC  = 192;
constexpr int cSS = 3;
constexpr int cNH = 6;
constexpr int cHD = 32;
constexpr int cN  = 49;
constexpr int cNW = 64;
constexpr int ROWS = cB * cNW * cN;   // 100352
constexpr float SCALE = 0.17677669529663687f;

// ---------------------------------------------------------------------------
// Scratch
// ---------------------------------------------------------------------------
__device__ float g_buf_a[(size_t)ROWS * cC];
__device__ float g_buf_b[(size_t)ROWS * cC];
__device__ float g_buf_big[(size_t)ROWS * 4 * cC];

// ---------------------------------------------------------------------------
// LayerNorm (+ optional shift + window partition gather)
// ---------------------------------------------------------------------------
template <bool SHIFT>
__global__ __launch_bounds__(192) void ln_kernel(
    const float* __restrict__ in, const float* __restrict__ g,
    const float* __restrict__ bb, float* __restrict__ out)
{
    const int r = blockIdx.x;
    size_t src;
    if (SHIFT) {
        int win = r / cN, n = r % cN;
        int b = win >> 6, wrem = win & 63;
        int wh = wrem >> 3, ww = wrem & 7;
        int ii = n / 7, jj = n % 7;
        int h = wh * 7 + ii + cSS; if (h >= cH) h -= cH;
        int w = ww * 7 + jj + cSS; if (w >= cW) w -= cW;
        src = (size_t)b * (cH * cW) + h * cW + w;
    } else {
        src = (size_t)r;
    }
    const int t = threadIdx.x;
    float v = in[src * cC + t];
    float s1 = v, s2 = v * v;
    #pragma unroll
    for (int o = 16; o; o >>= 1) {
        s1 += __shfl_xor_sync(0xffffffffu, s1, o);
        s2 += __shfl_xor_sync(0xffffffffu, s2, o);
    }
    __shared__ float sh1[6], sh2[6];
    const int wid = t >> 5, lane = t & 31;
    if (lane == 0) { sh1[wid] = s1; sh2[wid] = s2; }
    __syncthreads();
    float t1 = 0.f, t2 = 0.f;
    #pragma unroll
    for (int i = 0; i < 6; i++) { t1 += sh1[i]; t2 += sh2[i]; }
    const float mu  = t1 * (1.0f / cC);
    const float var = t2 * (1.0f / cC) - mu * mu;
    const float inv = rsqrtf(var + 1e-5f);
    out[(size_t)r * cC + t] = (v - mu) * inv * g[t] + bb[t];
}

// ---------------------------------------------------------------------------
// tf32 tensor-core GEMM.  C[M,N] = A[M,K] @ B[K,N]  (+ epilogue)
// BM=256 BN=64 BK=16, 8 warps (4x2), warp tile 64x32, m16n8k8 tf32 mma,
// 3-stage cp.async ring, one __syncthreads per k-tile.
// EPI 0: +bias   EPI 1: gelu(+bias)
// EPI 2: scatter(window reverse+unshift)+res   EPI 3: +bias+res[row]
// ---------------------------------------------------------------------------
#define CP_ASYNC16(dst_u32, src_ptr) \
    asm volatile("cp.async.cg.shared.global [%0], [%1], 16;\n" :: "r"(dst_u32), "l"(src_ptr))
#define CP_COMMIT() asm volatile("cp.async.commit_group;\n")
#define CP_WAIT(n)  asm volatile("cp.async.wait_group %0;\n" :: "n"(n))

__device__ __forceinline__ void mma_tf32(float c[4], const uint32_t a[4], const uint32_t b[2])
{
    asm volatile(
        "mma.sync.aligned.m16n8k8.row.col.f32.tf32.tf32.f32 "
        "{%0,%1,%2,%3}, {%4,%5,%6,%7}, {%8,%9}, {%0,%1,%2,%3};\n"
        : "+f"(c[0]), "+f"(c[1]), "+f"(c[2]), "+f"(c[3])
        : "r"(a[0]), "r"(a[1]), "r"(a[2]), "r"(a[3]), "r"(b[0]), "r"(b[1]));
}

constexpr int AS_S   = 20;   // 16 + 4 pad, 16B-aligned rows, conflict-free frag loads
constexpr int BS_S   = 72;   // 64 + 8 pad, 16B-aligned, conflict-free (8*dc+dg != 0 mod 32)
constexpr int STAGES = 3;
constexpr int A_ST   = 256 * AS_S;            // floats per A stage
constexpr int B_ST   = 16 * BS_S;             // floats per B stage
constexpr size_t GEMM_SMEM = (size_t)(STAGES * (A_ST + B_ST)) * 4;  // ~73.5 KB

template <int EPI>
__global__ __launch_bounds__(256, 2) void mma_gemm(
    const float* __restrict__ A, const float* __restrict__ Bm,
    const float* __restrict__ bias, const float* __restrict__ res,
    float* __restrict__ Cout, int Nn, int K)
{
    extern __shared__ float smem[];
    float* AsBase = smem;
    float* BsBase = smem + STAGES * A_ST;

    const int tid  = threadIdx.x;
    const int lane = tid & 31;
    const int warp = tid >> 5;
    const int wm = warp >> 1, wn = warp & 1;       // 4 x 2 warp grid
    const int g = lane >> 2, c = lane & 3;
    const int rowBase = blockIdx.y * 256;
    const int colBase = blockIdx.x * 64;

    float acc[4][4][4];
    #pragma unroll
    for (int i = 0; i < 4; i++)
        #pragma unroll
        for (int j = 0; j < 4; j++)
            #pragma unroll
            for (int l = 0; l < 4; l++) acc[i][j][l] = 0.f;

    const int aRow0  = tid >> 2;     // 0..63  (+64*r)
    const int aChunk = tid & 3;      // 16B chunk within k16
    const int bK     = tid >> 4;     // 0..15
    const int bCh    = tid & 15;     // 16B chunk within 64 cols
    const int S = K / 16;

    auto load_stage = [&](int buf, int k0) {
        float* As = AsBase + buf * A_ST;
        float* Bs = BsBase + buf * B_ST;
        #pragma unroll
        for (int r = 0; r < 4; r++) {
            const int row = aRow0 + 64 * r;
            const float* src = A + (size_t)(rowBase + row) * K + k0 + aChunk * 4;
            uint32_t dst = (uint32_t)__cvta_generic_to_shared(&As[row * AS_S + aChunk * 4]);
            CP_ASYNC16(dst, src);
        }
        {
            const float* src = Bm + (size_t)(k0 + bK) * Nn + colBase + bCh * 4;
            uint32_t dst = (uint32_t)__cvta_generic_to_shared(&Bs[bK * BS_S + bCh * 4]);
            CP_ASYNC16(dst, src);
        }
        CP_COMMIT();
    };

    load_stage(0, 0);
    if (S > 1) load_stage(1, 16);

    for (int s = 0; s < S; s++) {
        if (s + 1 < S) { CP_WAIT(1); } else { CP_WAIT(0); }
        __syncthreads();

        if (s + 2 < S) load_stage((s + 2) % STAGES, (s + 2) * 16);

        const float* as = AsBase + (s % STAGES) * A_ST;
        const float* bs = BsBase + (s % STAGES) * B_ST;
        #pragma unroll
        for (int ks = 0; ks < 2; ks++) {
            const int kb = ks * 8;
            uint32_t af[4][4], bf[4][2];
            #pragma unroll
            for (int mt = 0; mt < 4; mt++) {
                const int m0 = wm * 64 + mt * 16;
                af[mt][0] = __float_as_uint(as[(m0 + g    ) * AS_S + kb + c    ]);
                af[mt][1] = __float_as_uint(as[(m0 + g + 8) * AS_S + kb + c    ]);
                af[mt][2] = __float_as_uint(as[(m0 + g    ) * AS_S + kb + c + 4]);
                af[mt][3] = __float_as_uint(as[(m0 + g + 8) * AS_S + kb + c + 4]);
            }
            #pragma unroll
            for (int nt = 0; nt < 4; nt++) {
                const int n0 = wn * 32 + nt * 8 + g;
                bf[nt][0] = __float_as_uint(bs[(kb + c    ) * BS_S + n0]);
                bf[nt][1] = __float_as_uint(bs[(kb + c + 4) * BS_S + n0]);
            }
            #pragma unroll
            for (int mt = 0; mt < 4; mt++)
                #pragma unroll
                for (int nt = 0; nt < 4; nt++)
                    mma_tf32(acc[mt][nt], af[mt], bf[nt]);
        }
    }

    // ---- epilogue ----
    #pragma unroll
    for (int mt = 0; mt < 4; mt++) {
        #pragma unroll
        for (int half = 0; half < 2; half++) {
            const int r = rowBase + wm * 64 + mt * 16 + g + half * 8;
            size_t orow = (size_t)r;
            if (EPI == 2) {
                int win = r / cN, n = r % cN;
                int b = win >> 6, wrem = win & 63;
                int wh = wrem >> 3, ww = wrem & 7;
                int ii = n / 7, jj = n % 7;
                int h = wh * 7 + ii + cSS; if (h >= cH) h -= cH;
                int w = ww * 7 + jj + cSS; if (w >= cW) w -= cW;
                orow = (size_t)b * (cH * cW) + h * cW + w;
            }
            #pragma unroll
            for (int nt = 0; nt < 4; nt++) {
                const int col = colBase + wn * 32 + nt * 8 + 2 * c;
                float v0 = acc[mt][nt][half * 2 + 0] + bias[col];
                float v1 = acc[mt][nt][half * 2 + 1] + bias[col + 1];
                if (EPI == 1) {
                    v0 = 0.5f * v0 * (1.0f + erff(v0 * 0.70710678118654752f));
                    v1 = 0.5f * v1 * (1.0f + erff(v1 * 0.70710678118654752f));
                } else if (EPI == 2) {
                    v0 += res[orow * cC + col];
                    v1 += res[orow * cC + col + 1];
                } else if (EPI == 3) {
                    v0 += res[(size_t)r * Nn + col];
                    v1 += res[(size_t)r * Nn + col + 1];
                }
                float2 o; o.x = v0; o.y = v1;
                *(float2*)&Cout[orow * (size_t)Nn + col] = o;
            }
        }
    }
}

// ---------------------------------------------------------------------------
// Windowed attention: one block per (window, head)
// ---------------------------------------------------------------------------
__global__ __launch_bounds__(256) void attn_kernel(
    const float* __restrict__ qkv, const float* __restrict__ rpb,
    float* __restrict__ out)
{
    __shared__ float q[49][33], k[49][33], v[49][33];
    __shared__ float s[49][49];

    const int win = blockIdx.x, head = blockIdx.y;
    const int tid = threadIdx.x;
    const size_t base = (size_t)win * cN * (3 * cC) + head * cHD;

    for (int idx = tid; idx < cN * cHD; idx += 256) {
        int i = idx >> 5, d = idx & 31;
        size_t p = base + (size_t)i * (3 * cC) + d;
        q[i][d] = qkv[p];
        k[i][d] = qkv[p + cC];
        v[i][d] = qkv[p + 2 * cC];
    }
    __syncthreads();

    const int wrem = win & 63;
    const int wh = wrem >> 3, ww = wrem & 7;

    for (int idx = tid; idx < cN * cN; idx += 256) {
        int i = idx / cN, j = idx - cN * i;
        float acc = 0.f;
        #pragma unroll
        for (int d = 0; d < cHD; d++) acc += q[i][d] * k[j][d];
        acc *= SCALE;
        const int i1 = i / 7, j1 = i % 7, i2 = j / 7, j2 = j % 7;
        const int ridx = (i1 - i2 + 6) * 13 + (j1 - j2 + 6);
        acc += rpb[ridx * cNH + head];
        const int hi = wh * 7 + i1, hj = wh * 7 + i2;
        const int wi = ww * 7 + j1, wj = ww * 7 + j2;
        const int ci = (hi < 49 ? 0 : (hi < 53 ? 3 : 6)) + (wi < 49 ? 0 : (wi < 53 ? 1 : 2));
        const int cj = (hj < 49 ? 0 : (hj < 53 ? 3 : 6)) + (wj < 49 ? 0 : (wj < 53 ? 1 : 2));
        if (ci != cj) acc -= 100.0f;
        s[i][j] = acc;
    }
    __syncthreads();

    if (tid < cN) {
        float mx = -1e30f;
        #pragma unroll
        for (int j = 0; j < cN; j++) mx = fmaxf(mx, s[tid][j]);
        float sum = 0.f;
        #pragma unroll
        for (int j = 0; j < cN; j++) {
            float e = __expf(s[tid][j] - mx);
            s[tid][j] = e;
            sum += e;
        }
        const float rcp = 1.0f / sum;
        #pragma unroll
        for (int j = 0; j < cN; j++) s[tid][j] *= rcp;
    }
    __syncthreads();

    for (int idx = tid; idx < cN * cHD; idx += 256) {
        int i = idx >> 5, d = idx & 31;
        float acc = 0.f;
        #pragma unroll
        for (int j = 0; j < cN; j++) acc += s[i][j] * v[j][d];
        out[((size_t)win * cN + i) * cC + head * cHD + d] = acc;
    }
}

// ---------------------------------------------------------------------------
// Launch
// ---------------------------------------------------------------------------
extern "C" void kernel_launch(void* const* d_in, const int* in_sizes, int n_in,
                              void* d_out, int out_size)
{
    const float* x       = (const float*)d_in[0];
    const float* n1g     = (const float*)d_in[1];
    const float* n1b     = (const float*)d_in[2];
    const float* qkv_w   = (const float*)d_in[3];
    const float* qkv_b   = (const float*)d_in[4];
    const float* rpb     = (const float*)d_in[5];
    const float* proj_w  = (const float*)d_in[6];
    const float* proj_b  = (const float*)d_in[7];
    const float* n2g     = (const float*)d_in[8];
    const float* n2b     = (const float*)d_in[9];
    const float* fc1_w   = (const float*)d_in[10];
    const float* fc1_b   = (const float*)d_in[11];
    const float* fc2_w   = (const float*)d_in[12];
    const float* fc2_b   = (const float*)d_in[13];
    float* out = (float*)d_out;

    float *bufA, *bufB, *bufBig;
    cudaGetSymbolAddress((void**)&bufA,   g_buf_a);
    cudaGetSymbolAddress((void**)&bufB,   g_buf_b);
    cudaGetSymbolAddress((void**)&bufBig, g_buf_big);

    static bool attr_done = false;
    if (!attr_done) {
        cudaFuncSetAttribute(mma_gemm<0>, cudaFuncAttributeMaxDynamicSharedMemorySize, (int)GEMM_SMEM);
        cudaFuncSetAttribute(mma_gemm<1>, cudaFuncAttributeMaxDynamicSharedMemorySize, (int)GEMM_SMEM);
        cudaFuncSetAttribute(mma_gemm<2>, cudaFuncAttributeMaxDynamicSharedMemorySize, (int)GEMM_SMEM);
        cudaFuncSetAttribute(mma_gemm<3>, cudaFuncAttributeMaxDynamicSharedMemorySize, (int)GEMM_SMEM);
        attr_done = true;
    }

    const int MB = ROWS / 256; // 392

    ln_kernel<true><<<ROWS, 192>>>(x, n1g, n1b, bufA);
    mma_gemm<0><<<dim3(576 / 64, MB), 256, GEMM_SMEM>>>(bufA, qkv_w, qkv_b, nullptr, bufBig, 576, 192);
    attn_kernel<<<dim3(cB * cNW, cNH), 256>>>(bufBig, rpb, bufB);
    mma_gemm<2><<<dim3(192 / 64, MB), 256, GEMM_SMEM>>>(bufB, proj_w, proj_b, x, bufA, 192, 192);
    ln_kernel<false><<<ROWS, 192>>>(bufA, n2g, n2b, bufB);
    mma_gemm<1><<<dim3(768 / 64, MB), 256, GEMM_SMEM>>>(bufB, fc1_w, fc1_b, nullptr, bufBig, 768, 192);
    mma_gemm<3><<<dim3(192 / 64, MB), 256, GEMM_SMEM>>>(bufBig, fc2_w, fc2_b, bufA, out, 192, 768);
}

// round 6
// speedup vs baseline: 1.3398x; 1.3398x over previous
#include <cuda_runtime.h>
#include <cuda_fp16.h>
#include <math.h>
#include <stdint.h>

// ---------------------------------------------------------------------------
// Problem constants
// ---------------------------------------------------------------------------
constexpr int cB  = 32;
constexpr int cH  = 56;
constexpr int cW  = 56;
constexpr int cC  = 192;
constexpr int cSS = 3;
constexpr int cNH = 6;
constexpr int cHD = 32;
constexpr int cN  = 49;
constexpr int cNW = 64;
constexpr int ROWS = cB * cNW * cN;   // 100352
constexpr float SCALE = 0.17677669529663687f;

// ---------------------------------------------------------------------------
// Scratch (device globals)
// ---------------------------------------------------------------------------
__device__ __half g_h_a[(size_t)ROWS * cC];          // ln1 out (gemm A)
__device__ __half g_h_b[(size_t)ROWS * cC];          // attn out, then ln2 out
__device__ __half g_h_big[(size_t)ROWS * 4 * cC];    // qkv out (576), then fc1 out (768)
__device__ float  g_f_x1[(size_t)ROWS * cC];         // residual stream x1 (fp32)
// transposed half weights: qkv[576,192] | proj[192,192] | fc1[768,192] | fc2[192,768]
constexpr size_t WT_QKV  = 0;
constexpr size_t WT_PROJ = 576 * 192;
constexpr size_t WT_FC1  = WT_PROJ + 192 * 192;
constexpr size_t WT_FC2  = WT_FC1 + 768 * 192;
__device__ __half g_wT[WT_FC2 + 192 * 768];

// ---------------------------------------------------------------------------
// Weight transpose + fp16 convert: in[K,N] f32 -> out[N,K] f16
// ---------------------------------------------------------------------------
__global__ __launch_bounds__(256) void transpose_kernel(
    const float* __restrict__ in, __half* __restrict__ out, int K, int N)
{
    __shared__ float t[32][33];
    const int bx = blockIdx.x * 32;   // N
    const int by = blockIdx.y * 32;   // K
    const int x = threadIdx.x;
    for (int y = threadIdx.y; y < 32; y += 8)
        t[y][x] = in[(size_t)(by + y) * N + bx + x];
    __syncthreads();
    for (int y = threadIdx.y; y < 32; y += 8)
        out[(size_t)(bx + y) * K + by + x] = __float2half_rn(t[x][y]);
}

// ---------------------------------------------------------------------------
// LayerNorm (+ optional shift + window partition gather) -> fp16 out
// ---------------------------------------------------------------------------
template <bool SHIFT>
__global__ __launch_bounds__(192) void ln_kernel(
    const float* __restrict__ in, const float* __restrict__ g,
    const float* __restrict__ bb, __half* __restrict__ out)
{
    const int r = blockIdx.x;
    size_t src;
    if (SHIFT) {
        int win = r / cN, n = r % cN;
        int b = win >> 6, wrem = win & 63;
        int wh = wrem >> 3, ww = wrem & 7;
        int ii = n / 7, jj = n % 7;
        int h = wh * 7 + ii + cSS; if (h >= cH) h -= cH;
        int w = ww * 7 + jj + cSS; if (w >= cW) w -= cW;
        src = (size_t)b * (cH * cW) + h * cW + w;
    } else {
        src = (size_t)r;
    }
    const int t = threadIdx.x;
    float v = in[src * cC + t];
    float s1 = v, s2 = v * v;
    #pragma unroll
    for (int o = 16; o; o >>= 1) {
        s1 += __shfl_xor_sync(0xffffffffu, s1, o);
        s2 += __shfl_xor_sync(0xffffffffu, s2, o);
    }
    __shared__ float sh1[6], sh2[6];
    const int wid = t >> 5, lane = t & 31;
    if (lane == 0) { sh1[wid] = s1; sh2[wid] = s2; }
    __syncthreads();
    float t1 = 0.f, t2 = 0.f;
    #pragma unroll
    for (int i = 0; i < 6; i++) { t1 += sh1[i]; t2 += sh2[i]; }
    const float mu  = t1 * (1.0f / cC);
    const float var = t2 * (1.0f / cC) - mu * mu;
    const float inv = rsqrtf(var + 1e-5f);
    out[(size_t)r * cC + t] = __float2half_rn((v - mu) * inv * g[t] + bb[t]);
}

// ---------------------------------------------------------------------------
// fp16 tensor-core GEMM.  C[M,N] = A[M,K] @ Bt[N,K]^T  (+ epilogue)
// BM=128 BN=64 BK=32, 8 warps (4x2), warp tile 32x32, m16n8k16 f16 mma,
// ldmatrix.x4 fragment loads, 4-stage cp.async ring, 1 sync per k-tile.
// EPI 0: +bias -> half        EPI 1: gelu(+bias) -> half
// EPI 2: scatter(window reverse+unshift)+res -> f32   EPI 3: +bias+res -> f32
// ---------------------------------------------------------------------------
#define CP_ASYNC16(dst_u32, src_ptr) \
    asm volatile("cp.async.cg.shared.global [%0], [%1], 16;\n" :: "r"(dst_u32), "l"(src_ptr))
#define CP_COMMIT() asm volatile("cp.async.commit_group;\n")
#define CP_WAIT(n)  asm volatile("cp.async.wait_group %0;\n" :: "n"(n))

__device__ __forceinline__ void ldsm4(uint32_t r[4], uint32_t addr) {
    asm volatile("ldmatrix.sync.aligned.m8n8.x4.shared.b16 {%0,%1,%2,%3}, [%4];"
                 : "=r"(r[0]), "=r"(r[1]), "=r"(r[2]), "=r"(r[3]) : "r"(addr));
}

__device__ __forceinline__ void mma_f16(float c[4], const uint32_t a[4], const uint32_t b[2]) {
    asm volatile(
        "mma.sync.aligned.m16n8k16.row.col.f32.f16.f16.f32 "
        "{%0,%1,%2,%3}, {%4,%5,%6,%7}, {%8,%9}, {%0,%1,%2,%3};"
        : "+f"(c[0]), "+f"(c[1]), "+f"(c[2]), "+f"(c[3])
        : "r"(a[0]), "r"(a[1]), "r"(a[2]), "r"(a[3]), "r"(b[0]), "r"(b[1]));
}

// smem: 4 stages x (A 128x32 half = 8KB  +  B 64x32 half = 4KB) = 48 KB static
constexpr int STAGE_BYTES = 8192 + 4096;
constexpr int A_OFF = 0;
constexpr int B_OFF = 8192;

template <int EPI>
__global__ __launch_bounds__(256) void hgemm(
    const __half* __restrict__ A, const __half* __restrict__ Bt,
    const float* __restrict__ bias, const float* __restrict__ res,
    void* __restrict__ CoutV, int Nn, int K)
{
    __shared__ __align__(128) unsigned char smem[4 * STAGE_BYTES];
    const uint32_t sb = (uint32_t)__cvta_generic_to_shared(smem);

    const int tid  = threadIdx.x;
    const int lane = tid & 31;
    const int warp = tid >> 5;
    const int wm = warp >> 1, wn = warp & 1;   // 4 x 2 warps, warp tile 32x32
    const int sel = lane >> 3;                 // ldmatrix quadrant
    const int rowBase = blockIdx.y * 128;
    const int colBase = blockIdx.x * 64;
    const int S = K / 32;

    float acc[2][4][4];
    #pragma unroll
    for (int i = 0; i < 2; i++)
        #pragma unroll
        for (int j = 0; j < 4; j++)
            #pragma unroll
            for (int l = 0; l < 4; l++) acc[i][j][l] = 0.f;

    auto load_stage = [&](int buf, int k0) {
        const uint32_t aB = sb + buf * STAGE_BYTES + A_OFF;
        const uint32_t bB = sb + buf * STAGE_BYTES + B_OFF;
        #pragma unroll
        for (int i = 0; i < 2; i++) {
            const int cid = tid + i * 256;
            const int row = cid >> 2, ch = cid & 3;
            const __half* src = A + (size_t)(rowBase + row) * K + k0 + ch * 8;
            CP_ASYNC16(aB + row * 64 + ((ch ^ ((row >> 1) & 3)) << 4), src);
        }
        {
            const int row = tid >> 2, ch = tid & 3;
            const __half* src = Bt + (size_t)(colBase + row) * K + k0 + ch * 8;
            CP_ASYNC16(bB + row * 64 + ((ch ^ ((row >> 1) & 3)) << 4), src);
        }
        CP_COMMIT();
    };

    load_stage(0, 0);
    load_stage(1, 32);
    load_stage(2, 64);

    for (int s = 0; s < S; s++) {
        const int rem = S - 1 - s;
        if (rem >= 2) { CP_WAIT(2); } else if (rem == 1) { CP_WAIT(1); } else { CP_WAIT(0); }
        __syncthreads();
        if (s + 3 < S) load_stage((s + 3) & 3, (s + 3) * 32);

        const uint32_t aB = sb + (s & 3) * STAGE_BYTES + A_OFF;
        const uint32_t bB = sb + (s & 3) * STAGE_BYTES + B_OFF;
        #pragma unroll
        for (int kh = 0; kh < 2; kh++) {
            const int kc = kh * 2;   // 16B-chunk pair for this k16 step
            uint32_t af[2][4], bf[4][2];
            #pragma unroll
            for (int mt = 0; mt < 2; mt++) {
                const int arow = wm * 32 + mt * 16 + (lane & 7) + ((sel & 1) << 3);
                const int achk = kc + (sel >> 1);
                ldsm4(af[mt], aB + arow * 64 + ((achk ^ ((arow >> 1) & 3)) << 4));
            }
            #pragma unroll
            for (int np = 0; np < 2; np++) {
                const int brow = wn * 32 + np * 16 + (lane & 7) + ((sel >> 1) << 3);
                const int bchk = kc + (sel & 1);
                uint32_t t[4];
                ldsm4(t, bB + brow * 64 + ((bchk ^ ((brow >> 1) & 3)) << 4));
                bf[np * 2][0] = t[0]; bf[np * 2][1] = t[1];
                bf[np * 2 + 1][0] = t[2]; bf[np * 2 + 1][1] = t[3];
            }
            #pragma unroll
            for (int mt = 0; mt < 2; mt++)
                #pragma unroll
                for (int nt = 0; nt < 4; nt++)
                    mma_f16(acc[mt][nt], af[mt], bf[nt]);
        }
    }

    // ---- epilogue ----
    #pragma unroll
    for (int mt = 0; mt < 2; mt++) {
        #pragma unroll
        for (int h8 = 0; h8 < 2; h8++) {
            const int r = rowBase + wm * 32 + mt * 16 + (lane >> 2) + h8 * 8;
            size_t orow = (size_t)r;
            if (EPI == 2) {
                int win = r / cN, n = r % cN;
                int b = win >> 6, wrem = win & 63;
                int wh = wrem >> 3, ww = wrem & 7;
                int ii = n / 7, jj = n % 7;
                int h = wh * 7 + ii + cSS; if (h >= cH) h -= cH;
                int w = ww * 7 + jj + cSS; if (w >= cW) w -= cW;
                orow = (size_t)b * (cH * cW) + h * cW + w;
            }
            #pragma unroll
            for (int nt = 0; nt < 4; nt++) {
                const int col = colBase + wn * 32 + nt * 8 + (lane & 3) * 2;
                float v0 = acc[mt][nt][h8 * 2 + 0] + bias[col];
                float v1 = acc[mt][nt][h8 * 2 + 1] + bias[col + 1];
                if (EPI == 0) {
                    *(__half2*)((__half*)CoutV + orow * (size_t)Nn + col) =
                        __floats2half2_rn(v0, v1);
                } else if (EPI == 1) {
                    v0 = 0.5f * v0 * (1.0f + erff(v0 * 0.70710678118654752f));
                    v1 = 0.5f * v1 * (1.0f + erff(v1 * 0.70710678118654752f));
                    *(__half2*)((__half*)CoutV + orow * (size_t)Nn + col) =
                        __floats2half2_rn(v0, v1);
                } else if (EPI == 2) {
                    v0 += res[orow * cC + col];
                    v1 += res[orow * cC + col + 1];
                    float2 o; o.x = v0; o.y = v1;
                    *(float2*)((float*)CoutV + orow * (size_t)Nn + col) = o;
                } else {
                    v0 += res[(size_t)r * Nn + col];
                    v1 += res[(size_t)r * Nn + col + 1];
                    float2 o; o.x = v0; o.y = v1;
                    *(float2*)((float*)CoutV + orow * (size_t)Nn + col) = o;
                }
            }
        }
    }
}

// ---------------------------------------------------------------------------
// Windowed attention: one block per (window, head); fp16 in/out, fp32 math
// ---------------------------------------------------------------------------
__global__ __launch_bounds__(256) void attn_kernel(
    const __half* __restrict__ qkv, const float* __restrict__ rpb,
    __half* __restrict__ out)
{
    __shared__ float q[49][33], k[49][33], v[49][33];
    __shared__ float s[49][49];

    const int win = blockIdx.x, head = blockIdx.y;
    const int tid = threadIdx.x;
    const size_t base = (size_t)win * cN * (3 * cC) + head * cHD;

    for (int idx = tid; idx < cN * cHD; idx += 256) {
        int i = idx >> 5, d = idx & 31;
        size_t p = base + (size_t)i * (3 * cC) + d;
        q[i][d] = __half2float(qkv[p]);
        k[i][d] = __half2float(qkv[p + cC]);
        v[i][d] = __half2float(qkv[p + 2 * cC]);
    }
    __syncthreads();

    const int wrem = win & 63;
    const int wh = wrem >> 3, ww = wrem & 7;

    for (int idx = tid; idx < cN * cN; idx += 256) {
        int i = idx / cN, j = idx - cN * i;
        float acc = 0.f;
        #pragma unroll
        for (int d = 0; d < cHD; d++) acc += q[i][d] * k[j][d];
        acc *= SCALE;
        const int i1 = i / 7, j1 = i % 7, i2 = j / 7, j2 = j % 7;
        const int ridx = (i1 - i2 + 6) * 13 + (j1 - j2 + 6);
        acc += rpb[ridx * cNH + head];
        const int hi = wh * 7 + i1, hj = wh * 7 + i2;
        const int wi = ww * 7 + j1, wj = ww * 7 + j2;
        const int ci = (hi < 49 ? 0 : (hi < 53 ? 3 : 6)) + (wi < 49 ? 0 : (wi < 53 ? 1 : 2));
        const int cj = (hj < 49 ? 0 : (hj < 53 ? 3 : 6)) + (wj < 49 ? 0 : (wj < 53 ? 1 : 2));
        if (ci != cj) acc -= 100.0f;
        s[i][j] = acc;
    }
    __syncthreads();

    if (tid < cN) {
        float mx = -1e30f;
        #pragma unroll
        for (int j = 0; j < cN; j++) mx = fmaxf(mx, s[tid][j]);
        float sum = 0.f;
        #pragma unroll
        for (int j = 0; j < cN; j++) {
            float e = __expf(s[tid][j] - mx);
            s[tid][j] = e;
            sum += e;
        }
        const float rcp = 1.0f / sum;
        #pragma unroll
        for (int j = 0; j < cN; j++) s[tid][j] *= rcp;
    }
    __syncthreads();

    for (int idx = tid; idx < cN * cHD; idx += 256) {
        int i = idx >> 5, d = idx & 31;
        float acc = 0.f;
        #pragma unroll
        for (int j = 0; j < cN; j++) acc += s[i][j] * v[j][d];
        out[((size_t)win * cN + i) * cC + head * cHD + d] = __float2half_rn(acc);
    }
}

// ---------------------------------------------------------------------------
// Launch
// ---------------------------------------------------------------------------
extern "C" void kernel_launch(void* const* d_in, const int* in_sizes, int n_in,
                              void* d_out, int out_size)
{
    const float* x       = (const float*)d_in[0];
    const float* n1g     = (const float*)d_in[1];
    const float* n1b     = (const float*)d_in[2];
    const float* qkv_w   = (const float*)d_in[3];
    const float* qkv_b   = (const float*)d_in[4];
    const float* rpb     = (const float*)d_in[5];
    const float* proj_w  = (const float*)d_in[6];
    const float* proj_b  = (const float*)d_in[7];
    const float* n2g     = (const float*)d_in[8];
    const float* n2b     = (const float*)d_in[9];
    const float* fc1_w   = (const float*)d_in[10];
    const float* fc1_b   = (const float*)d_in[11];
    const float* fc2_w   = (const float*)d_in[12];
    const float* fc2_b   = (const float*)d_in[13];
    float* out = (float*)d_out;

    __half *hA, *hB, *hBig, *wT;
    float *fX1;
    cudaGetSymbolAddress((void**)&hA,   g_h_a);
    cudaGetSymbolAddress((void**)&hB,   g_h_b);
    cudaGetSymbolAddress((void**)&hBig, g_h_big);
    cudaGetSymbolAddress((void**)&fX1,  g_f_x1);
    cudaGetSymbolAddress((void**)&wT,   g_wT);

    // weight transposes + f16 conversion ([K,N] -> [N,K])
    transpose_kernel<<<dim3(576 / 32, 192 / 32), dim3(32, 8)>>>(qkv_w, wT + WT_QKV, 192, 576);
    transpose_kernel<<<dim3(192 / 32, 192 / 32), dim3(32, 8)>>>(proj_w, wT + WT_PROJ, 192, 192);
    transpose_kernel<<<dim3(768 / 32, 192 / 32), dim3(32, 8)>>>(fc1_w, wT + WT_FC1, 192, 768);
    transpose_kernel<<<dim3(192 / 32, 768 / 32), dim3(32, 8)>>>(fc2_w, wT + WT_FC2, 768, 192);

    const int MB = ROWS / 128; // 784

    ln_kernel<true><<<ROWS, 192>>>(x, n1g, n1b, hA);
    hgemm<0><<<dim3(576 / 64, MB), 256>>>(hA, wT + WT_QKV, qkv_b, nullptr, hBig, 576, 192);
    attn_kernel<<<dim3(cB * cNW, cNH), 256>>>(hBig, rpb, hB);
    hgemm<2><<<dim3(192 / 64, MB), 256>>>(hB, wT + WT_PROJ, proj_b, x, fX1, 192, 192);
    ln_kernel<false><<<ROWS, 192>>>(fX1, n2g, n2b, hB);
    hgemm<1><<<dim3(768 / 64, MB), 256>>>(hB, wT + WT_FC1, fc1_b, nullptr, hBig, 768, 192);
    hgemm<3><<<dim3(192 / 64, MB), 256>>>(hBig, wT + WT_FC2, fc2_b, fX1, out, 192, 768);
}

// round 7
// speedup vs baseline: 1.3399x; 1.0001x over previous
#include <cuda_runtime.h>
#include <cuda_fp16.h>
#include <math.h>
#include <stdint.h>

// ---------------------------------------------------------------------------
// Problem constants
// ---------------------------------------------------------------------------
constexpr int cB  = 32;
constexpr int cH  = 56;
constexpr int cW  = 56;
constexpr int cC  = 192;
constexpr int cSS = 3;
constexpr int cNH = 6;
constexpr int cHD = 32;
constexpr int cN  = 49;
constexpr int cNW = 64;
constexpr int ROWS = cB * cNW * cN;   // 100352
constexpr float SCALE = 0.17677669529663687f;

// ---------------------------------------------------------------------------
// Scratch (device globals)
// ---------------------------------------------------------------------------
__device__ __half g_h_a[(size_t)ROWS * cC];          // ln1 out (gemm A)
__device__ __half g_h_b[(size_t)ROWS * cC];          // attn out, then ln2 out
__device__ __half g_h_big[(size_t)ROWS * 4 * cC];    // qkv out (576), then fc1 out (768)
__device__ float  g_f_x1[(size_t)ROWS * cC];         // residual stream x1 (fp32)
// transposed half weights: qkv[576,192] | proj[192,192] | fc1[768,192] | fc2[192,768]
constexpr size_t WT_QKV  = 0;
constexpr size_t WT_PROJ = 576 * 192;
constexpr size_t WT_FC1  = WT_PROJ + 192 * 192;
constexpr size_t WT_FC2  = WT_FC1 + 768 * 192;
__device__ __half g_wT[WT_FC2 + 192 * 768];

// ---------------------------------------------------------------------------
// Weight transpose + fp16 convert: in[K,N] f32 -> out[N,K] f16
// ---------------------------------------------------------------------------
__global__ __launch_bounds__(256) void transpose_kernel(
    const float* __restrict__ in, __half* __restrict__ out, int K, int N)
{
    __shared__ float t[32][33];
    const int bx = blockIdx.x * 32;   // N
    const int by = blockIdx.y * 32;   // K
    const int x = threadIdx.x;
    for (int y = threadIdx.y; y < 32; y += 8)
        t[y][x] = in[(size_t)(by + y) * N + bx + x];
    __syncthreads();
    for (int y = threadIdx.y; y < 32; y += 8)
        out[(size_t)(bx + y) * K + by + x] = __float2half_rn(t[x][y]);
}

// ---------------------------------------------------------------------------
// LayerNorm (+ optional shift + window partition gather) -> fp16 out
// ---------------------------------------------------------------------------
template <bool SHIFT>
__global__ __launch_bounds__(192) void ln_kernel(
    const float* __restrict__ in, const float* __restrict__ g,
    const float* __restrict__ bb, __half* __restrict__ out)
{
    const int r = blockIdx.x;
    size_t src;
    if (SHIFT) {
        int win = r / cN, n = r % cN;
        int b = win >> 6, wrem = win & 63;
        int wh = wrem >> 3, ww = wrem & 7;
        int ii = n / 7, jj = n % 7;
        int h = wh * 7 + ii + cSS; if (h >= cH) h -= cH;
        int w = ww * 7 + jj + cSS; if (w >= cW) w -= cW;
        src = (size_t)b * (cH * cW) + h * cW + w;
    } else {
        src = (size_t)r;
    }
    const int t = threadIdx.x;
    float v = in[src * cC + t];
    float s1 = v, s2 = v * v;
    #pragma unroll
    for (int o = 16; o; o >>= 1) {
        s1 += __shfl_xor_sync(0xffffffffu, s1, o);
        s2 += __shfl_xor_sync(0xffffffffu, s2, o);
    }
    __shared__ float sh1[6], sh2[6];
    const int wid = t >> 5, lane = t & 31;
    if (lane == 0) { sh1[wid] = s1; sh2[wid] = s2; }
    __syncthreads();
    float t1 = 0.f, t2 = 0.f;
    #pragma unroll
    for (int i = 0; i < 6; i++) { t1 += sh1[i]; t2 += sh2[i]; }
    const float mu  = t1 * (1.0f / cC);
    const float var = t2 * (1.0f / cC) - mu * mu;
    const float inv = rsqrtf(var + 1e-5f);
    out[(size_t)r * cC + t] = __float2half_rn((v - mu) * inv * g[t] + bb[t]);
}

// ---------------------------------------------------------------------------
// fp16 tensor-core GEMM.  C[M,N] = A[M,K] @ Bt[N,K]^T  (+ epilogue)
// BM=128 BN=64 BK=32, 8 warps (4x2), warp tile 32x32, m16n8k16 f16 mma,
// ldmatrix.x4 fragment loads, 4-stage cp.async ring, 1 sync per k-tile.
// EPI 0: +bias -> half        EPI 1: gelu(+bias) -> half
// EPI 2: scatter(window reverse+unshift)+res -> f32   EPI 3: +bias+res -> f32
// ---------------------------------------------------------------------------
#define CP_ASYNC16(dst_u32, src_ptr) \
    asm volatile("cp.async.cg.shared.global [%0], [%1], 16;\n" :: "r"(dst_u32), "l"(src_ptr))
#define CP_COMMIT() asm volatile("cp.async.commit_group;\n")
#define CP_WAIT(n)  asm volatile("cp.async.wait_group %0;\n" :: "n"(n))

__device__ __forceinline__ void ldsm4(uint32_t r[4], uint32_t addr) {
    asm volatile("ldmatrix.sync.aligned.m8n8.x4.shared.b16 {%0,%1,%2,%3}, [%4];"
                 : "=r"(r[0]), "=r"(r[1]), "=r"(r[2]), "=r"(r[3]) : "r"(addr));
}

__device__ __forceinline__ void mma_f16(float c[4], const uint32_t a[4], const uint32_t b[2]) {
    asm volatile(
        "mma.sync.aligned.m16n8k16.row.col.f32.f16.f16.f32 "
        "{%0,%1,%2,%3}, {%4,%5,%6,%7}, {%8,%9}, {%0,%1,%2,%3};"
        : "+f"(c[0]), "+f"(c[1]), "+f"(c[2]), "+f"(c[3])
        : "r"(a[0]), "r"(a[1]), "r"(a[2]), "r"(a[3]), "r"(b[0]), "r"(b[1]));
}

// smem: 4 stages x (A 128x32 half = 8KB  +  B 64x32 half = 4KB) = 48 KB static
constexpr int STAGE_BYTES = 8192 + 4096;
constexpr int A_OFF = 0;
constexpr int B_OFF = 8192;

template <int EPI>
__global__ __launch_bounds__(256) void hgemm(
    const __half* __restrict__ A, const __half* __restrict__ Bt,
    const float* __restrict__ bias, const float* __restrict__ res,
    void* __restrict__ CoutV, int Nn, int K)
{
    __shared__ __align__(128) unsigned char smem[4 * STAGE_BYTES];
    const uint32_t sb = (uint32_t)__cvta_generic_to_shared(smem);

    const int tid  = threadIdx.x;
    const int lane = tid & 31;
    const int warp = tid >> 5;
    const int wm = warp >> 1, wn = warp & 1;   // 4 x 2 warps, warp tile 32x32
    const int sel = lane >> 3;                 // ldmatrix quadrant
    const int rowBase = blockIdx.y * 128;
    const int colBase = blockIdx.x * 64;
    const int S = K / 32;

    float acc[2][4][4];
    #pragma unroll
    for (int i = 0; i < 2; i++)
        #pragma unroll
        for (int j = 0; j < 4; j++)
            #pragma unroll
            for (int l = 0; l < 4; l++) acc[i][j][l] = 0.f;

    auto load_stage = [&](int buf, int k0) {
        const uint32_t aB = sb + buf * STAGE_BYTES + A_OFF;
        const uint32_t bB = sb + buf * STAGE_BYTES + B_OFF;
        #pragma unroll
        for (int i = 0; i < 2; i++) {
            const int cid = tid + i * 256;
            const int row = cid >> 2, ch = cid & 3;
            const __half* src = A + (size_t)(rowBase + row) * K + k0 + ch * 8;
            CP_ASYNC16(aB + row * 64 + ((ch ^ ((row >> 1) & 3)) << 4), src);
        }
        {
            const int row = tid >> 2, ch = tid & 3;
            const __half* src = Bt + (size_t)(colBase + row) * K + k0 + ch * 8;
            CP_ASYNC16(bB + row * 64 + ((ch ^ ((row >> 1) & 3)) << 4), src);
        }
        CP_COMMIT();
    };

    load_stage(0, 0);
    load_stage(1, 32);
    load_stage(2, 64);

    for (int s = 0; s < S; s++) {
        const int rem = S - 1 - s;
        if (rem >= 2) { CP_WAIT(2); } else if (rem == 1) { CP_WAIT(1); } else { CP_WAIT(0); }
        __syncthreads();
        if (s + 3 < S) load_stage((s + 3) & 3, (s + 3) * 32);

        const uint32_t aB = sb + (s & 3) * STAGE_BYTES + A_OFF;
        const uint32_t bB = sb + (s & 3) * STAGE_BYTES + B_OFF;
        #pragma unroll
        for (int kh = 0; kh < 2; kh++) {
            const int kc = kh * 2;   // 16B-chunk pair for this k16 step
            uint32_t af[2][4], bf[4][2];
            #pragma unroll
            for (int mt = 0; mt < 2; mt++) {
                const int arow = wm * 32 + mt * 16 + (lane & 7) + ((sel & 1) << 3);
                const int achk = kc + (sel >> 1);
                ldsm4(af[mt], aB + arow * 64 + ((achk ^ ((arow >> 1) & 3)) << 4));
            }
            #pragma unroll
            for (int np = 0; np < 2; np++) {
                const int brow = wn * 32 + np * 16 + (lane & 7) + ((sel >> 1) << 3);
                const int bchk = kc + (sel & 1);
                uint32_t t[4];
                ldsm4(t, bB + brow * 64 + ((bchk ^ ((brow >> 1) & 3)) << 4));
                bf[np * 2][0] = t[0]; bf[np * 2][1] = t[1];
                bf[np * 2 + 1][0] = t[2]; bf[np * 2 + 1][1] = t[3];
            }
            #pragma unroll
            for (int mt = 0; mt < 2; mt++)
                #pragma unroll
                for (int nt = 0; nt < 4; nt++)
                    mma_f16(acc[mt][nt], af[mt], bf[nt]);
        }
    }

    // ---- epilogue ----
    #pragma unroll
    for (int mt = 0; mt < 2; mt++) {
        #pragma unroll
        for (int h8 = 0; h8 < 2; h8++) {
            const int r = rowBase + wm * 32 + mt * 16 + (lane >> 2) + h8 * 8;
            size_t orow = (size_t)r;
            if (EPI == 2) {
                int win = r / cN, n = r % cN;
                int b = win >> 6, wrem = win & 63;
                int wh = wrem >> 3, ww = wrem & 7;
                int ii = n / 7, jj = n % 7;
                int h = wh * 7 + ii + cSS; if (h >= cH) h -= cH;
                int w = ww * 7 + jj + cSS; if (w >= cW) w -= cW;
                orow = (size_t)b * (cH * cW) + h * cW + w;
            }
            #pragma unroll
            for (int nt = 0; nt < 4; nt++) {
                const int col = colBase + wn * 32 + nt * 8 + (lane & 3) * 2;
                float v0 = acc[mt][nt][h8 * 2 + 0] + bias[col];
                float v1 = acc[mt][nt][h8 * 2 + 1] + bias[col + 1];
                if (EPI == 0) {
                    *(__half2*)((__half*)CoutV + orow * (size_t)Nn + col) =
                        __floats2half2_rn(v0, v1);
                } else if (EPI == 1) {
                    v0 = 0.5f * v0 * (1.0f + erff(v0 * 0.70710678118654752f));
                    v1 = 0.5f * v1 * (1.0f + erff(v1 * 0.70710678118654752f));
                    *(__half2*)((__half*)CoutV + orow * (size_t)Nn + col) =
                        __floats2half2_rn(v0, v1);
                } else if (EPI == 2) {
                    v0 += res[orow * cC + col];
                    v1 += res[orow * cC + col + 1];
                    float2 o; o.x = v0; o.y = v1;
                    *(float2*)((float*)CoutV + orow * (size_t)Nn + col) = o;
                } else {
                    v0 += res[(size_t)r * Nn + col];
                    v1 += res[(size_t)r * Nn + col + 1];
                    float2 o; o.x = v0; o.y = v1;
                    *(float2*)((float*)CoutV + orow * (size_t)Nn + col) = o;
                }
            }
        }
    }
}

// ---------------------------------------------------------------------------
// Windowed attention: one block per (window, head); fp16 in/out, fp32 math
// ---------------------------------------------------------------------------
__global__ __launch_bounds__(256) void attn_kernel(
    const __half* __restrict__ qkv, const float* __restrict__ rpb,
    __half* __restrict__ out)
{
    __shared__ float q[49][33], k[49][33], v[49][33];
    __shared__ float s[49][49];

    const int win = blockIdx.x, head = blockIdx.y;
    const int tid = threadIdx.x;
    const size_t base = (size_t)win * cN * (3 * cC) + head * cHD;

    for (int idx = tid; idx < cN * cHD; idx += 256) {
        int i = idx >> 5, d = idx & 31;
        size_t p = base + (size_t)i * (3 * cC) + d;
        q[i][d] = __half2float(qkv[p]);
        k[i][d] = __half2float(qkv[p + cC]);
        v[i][d] = __half2float(qkv[p + 2 * cC]);
    }
    __syncthreads();

    const int wrem = win & 63;
    const int wh = wrem >> 3, ww = wrem & 7;

    for (int idx = tid; idx < cN * cN; idx += 256) {
        int i = idx / cN, j = idx - cN * i;
        float acc = 0.f;
        #pragma unroll
        for (int d = 0; d < cHD; d++) acc += q[i][d] * k[j][d];
        acc *= SCALE;
        const int i1 = i / 7, j1 = i % 7, i2 = j / 7, j2 = j % 7;
        const int ridx = (i1 - i2 + 6) * 13 + (j1 - j2 + 6);
        acc += rpb[ridx * cNH + head];
        const int hi = wh * 7 + i1, hj = wh * 7 + i2;
        const int wi = ww * 7 + j1, wj = ww * 7 + j2;
        const int ci = (hi < 49 ? 0 : (hi < 53 ? 3 : 6)) + (wi < 49 ? 0 : (wi < 53 ? 1 : 2));
        const int cj = (hj < 49 ? 0 : (hj < 53 ? 3 : 6)) + (wj < 49 ? 0 : (wj < 53 ? 1 : 2));
        if (ci != cj) acc -= 100.0f;
        s[i][j] = acc;
    }
    __syncthreads();

    if (tid < cN) {
        float mx = -1e30f;
        #pragma unroll
        for (int j = 0; j < cN; j++) mx = fmaxf(mx, s[tid][j]);
        float sum = 0.f;
        #pragma unroll
        for (int j = 0; j < cN; j++) {
            float e = __expf(s[tid][j] - mx);
            s[tid][j] = e;
            sum += e;
        }
        const float rcp = 1.0f / sum;
        #pragma unroll
        for (int j = 0; j < cN; j++) s[tid][j] *= rcp;
    }
    __syncthreads();

    for (int idx = tid; idx < cN * cHD; idx += 256) {
        int i = idx >> 5, d = idx & 31;
        float acc = 0.f;
        #pragma unroll
        for (int j = 0; j < cN; j++) acc += s[i][j] * v[j][d];
        out[((size_t)win * cN + i) * cC + head * cHD + d] = __float2half_rn(acc);
    }
}

// ---------------------------------------------------------------------------
// Launch
// ---------------------------------------------------------------------------
extern "C" void kernel_launch(void* const* d_in, const int* in_sizes, int n_in,
                              void* d_out, int out_size)
{
    const float* x       = (const float*)d_in[0];
    const float* n1g     = (const float*)d_in[1];
    const float* n1b     = (const float*)d_in[2];
    const float* qkv_w   = (const float*)d_in[3];
    const float* qkv_b   = (const float*)d_in[4];
    const float* rpb     = (const float*)d_in[5];
    const float* proj_w  = (const float*)d_in[6];
    const float* proj_b  = (const float*)d_in[7];
    const float* n2g     = (const float*)d_in[8];
    const float* n2b     = (const float*)d_in[9];
    const float* fc1_w   = (const float*)d_in[10];
    const float* fc1_b   = (const float*)d_in[11];
    const float* fc2_w   = (const float*)d_in[12];
    const float* fc2_b   = (const float*)d_in[13];
    float* out = (float*)d_out;

    __half *hA, *hB, *hBig, *wT;
    float *fX1;
    cudaGetSymbolAddress((void**)&hA,   g_h_a);
    cudaGetSymbolAddress((void**)&hB,   g_h_b);
    cudaGetSymbolAddress((void**)&hBig, g_h_big);
    cudaGetSymbolAddress((void**)&fX1,  g_f_x1);
    cudaGetSymbolAddress((void**)&wT,   g_wT);

    // weight transposes + f16 conversion ([K,N] -> [N,K])
    transpose_kernel<<<dim3(576 / 32, 192 / 32), dim3(32, 8)>>>(qkv_w, wT + WT_QKV, 192, 576);
    transpose_kernel<<<dim3(192 / 32, 192 / 32), dim3(32, 8)>>>(proj_w, wT + WT_PROJ, 192, 192);
    transpose_kernel<<<dim3(768 / 32, 192 / 32), dim3(32, 8)>>>(fc1_w, wT + WT_FC1, 192, 768);
    transpose_kernel<<<dim3(192 / 32, 768 / 32), dim3(32, 8)>>>(fc2_w, wT + WT_FC2, 768, 192);

    const int MB = ROWS / 128; // 784

    ln_kernel<true><<<ROWS, 192>>>(x, n1g, n1b, hA);
    hgemm<0><<<dim3(576 / 64, MB), 256>>>(hA, wT + WT_QKV, qkv_b, nullptr, hBig, 576, 192);
    attn_kernel<<<dim3(cB * cNW, cNH), 256>>>(hBig, rpb, hB);
    hgemm<2><<<dim3(192 / 64, MB), 256>>>(hB, wT + WT_PROJ, proj_b, x, fX1, 192, 192);
    ln_kernel<false><<<ROWS, 192>>>(fX1, n2g, n2b, hB);
    hgemm<1><<<dim3(768 / 64, MB), 256>>>(hB, wT + WT_FC1, fc1_b, nullptr, hBig, 768, 192);
    hgemm<3><<<dim3(192 / 64, MB), 256>>>(hBig, wT + WT_FC2, fc2_b, fX1, out, 192, 768);
}